// round 2
// baseline (speedup 1.0000x reference)
#include <cuda_runtime.h>
#include <cstdint>

#define BB 16
#define TT 64
#define CC 512
#define GPITCH 65   // padded row pitch (floats) for transposed g tile: kills 32-way STS conflicts

// Scratch (allocation-free rule: __device__ globals)
__device__ float g_VE[BB * TT * CC];   // x @ W_proj + b_proj
__device__ float g_XE[BB * TT * CC];   // x @ W_x    + b_x

// ---------------------------------------------------------------------------
// Kernel 1: both embedding GEMMs fused. 128 blocks x 8 rows, 512 threads.
// thread c owns output column c for 8 rows of both matrices.
// ---------------------------------------------------------------------------
__global__ __launch_bounds__(512) void embed_kernel(
    const float* __restrict__ x,
    const float* __restrict__ Wp, const float* __restrict__ bp,
    const float* __restrict__ Wx, const float* __restrict__ bx)
{
    __shared__ float xs[8 * CC];
    const int tid = threadIdx.x;
    const int r0  = blockIdx.x * 8;

    for (int idx = tid; idx < 8 * CC; idx += 512) xs[idx] = x[r0 * CC + idx];
    __syncthreads();

    const int c = tid;
    float accP[8], accX[8];
#pragma unroll
    for (int r = 0; r < 8; r++) { accP[r] = 0.f; accX[r] = 0.f; }

#pragma unroll 2
    for (int k = 0; k < CC; k++) {
        const float wp = Wp[k * CC + c];
        const float wx = Wx[k * CC + c];
#pragma unroll
        for (int r = 0; r < 8; r++) {
            const float xv = xs[r * CC + k];           // smem broadcast
            accP[r] = fmaf(xv, wp, accP[r]);
            accX[r] = fmaf(xv, wx, accX[r]);
        }
    }

    const float bpv = bp[c], bxv = bx[c];
#pragma unroll
    for (int r = 0; r < 8; r++) {
        g_VE[(r0 + r) * CC + c] = accP[r] + bpv;
        g_XE[(r0 + r) * CC + c] = accX[r] + bxv;
    }
}

// ---------------------------------------------------------------------------
// Kernel 2: one CTA per (b, i). Fused feature build + [64,512]x[512,512] GEMM
// (f32x2 packed FFMA) + sigmoid/mask + logsumexp + mean-over-C.
// ---------------------------------------------------------------------------
__global__ __launch_bounds__(512) void temporal_kernel(
    const float* __restrict__ x,
    const float* __restrict__ ts,
    const float* __restrict__ amask,
    const float* __restrict__ Wt,  const float* __restrict__ bt,
    const float* __restrict__ Wim, const float* __restrict__ bim,
    float* __restrict__ out)
{
    extern __shared__ float sm[];
    float* g     = sm;                    // [512][GPITCH] transposed relu(h); later reused as z[64][512]
    float* feat0 = sm + CC * GPITCH;      // 64
    float* feat1 = feat0 + TT;            // 64
    float* maskv = feat1 + TT;            // 64
    float* sout2 = maskv + TT;            // 64

    const int tid = threadIdx.x;
    const int b   = blockIdx.x >> 6;
    const int i   = blockIdx.x & 63;

    if (tid < TT) {
        const float ti  = ts[b * TT + i];
        const float tj  = ts[b * TT + tid];
        const float rel = ti - tj;
        feat0[tid] = log1pf(fmaxf(rel, 0.f));
        feat1[tid] = log1pf(fmaxf(-rel, 0.f));
        maskv[tid] = amask[b * TT + tid];
        sout2[tid] = 0.f;
    }
    __syncthreads();

    // ---- build g^T[k][j] = relu( f0[j]*Wt[0][k] + f1[j]*Wt[1][k] + bt[k] + XE[b][j][k] )
    {
        const int ck = tid;
        const float w0 = Wt[ck], w1 = Wt[CC + ck], b0 = bt[ck];
        const float* XEb = g_XE + b * TT * CC;
#pragma unroll 4
        for (int j = 0; j < TT; j++) {
            const float h = fmaf(feat0[j], w0, fmaf(feat1[j], w1, b0)) + XEb[j * CC + ck];
            g[ck * GPITCH + j] = fmaxf(h, 0.f);
        }
    }
    __syncthreads();

    // ---- GEMM: out[j][n] = sum_k g[j][k] * Wim[k][n], 8j x 8n per thread
    const int tc = tid & 63;      // n-group 0..63
    const int tjg = tid >> 6;     // j-group 0..7 (warp-uniform)
    const int j0 = tjg * 8;
    const int c0 = tc * 8;

    unsigned long long acc[8][4];
#pragma unroll
    for (int jj = 0; jj < 8; jj++)
#pragma unroll
        for (int cp = 0; cp < 4; cp++) acc[jj][cp] = 0ull;

    const float* Wbase = Wim + c0;
#pragma unroll 2
    for (int k = 0; k < CC; k++) {
        const ulonglong2* wrow = reinterpret_cast<const ulonglong2*>(Wbase + (size_t)k * CC);
        const ulonglong2 wA = wrow[0];   // (w[c0],w[c0+1]) , (w[c0+2],w[c0+3])
        const ulonglong2 wB = wrow[1];
        const float* grow = g + k * GPITCH + j0;
#pragma unroll
        for (int jj = 0; jj < 8; jj++) {
            const float gv = grow[jj];   // smem broadcast (all lanes same j-group? lanes share tjg)
            unsigned long long gp;
            asm("mov.b64 %0, {%1, %1};" : "=l"(gp) : "r"(__float_as_uint(gv)));
            asm("fma.rn.f32x2 %0, %1, %2, %0;" : "+l"(acc[jj][0]) : "l"(gp), "l"(wA.x));
            asm("fma.rn.f32x2 %0, %1, %2, %0;" : "+l"(acc[jj][1]) : "l"(gp), "l"(wA.y));
            asm("fma.rn.f32x2 %0, %1, %2, %0;" : "+l"(acc[jj][2]) : "l"(gp), "l"(wB.x));
            asm("fma.rn.f32x2 %0, %1, %2, %0;" : "+l"(acc[jj][3]) : "l"(gp), "l"(wB.y));
        }
    }
    __syncthreads();   // all g reads finished before we overwrite the region with z

    // ---- epilogue: p = sigmoid(s + b_imp)*mask; z = VE*p; psum for out2
    float bi[8];
#pragma unroll
    for (int cc = 0; cc < 8; cc++) bi[cc] = bim[c0 + cc];

    const float* VEb = g_VE + b * TT * CC;
    float* zbuf = sm;   // reuse as z[j][c], pitch CC (32768 floats < 33280)

    float psum[8];
#pragma unroll
    for (int jj = 0; jj < 8; jj++) {
        const int j = j0 + jj;
        const float mk = maskv[j];
        const float4 ve0 = *reinterpret_cast<const float4*>(VEb + j * CC + c0);
        const float4 ve1 = *reinterpret_cast<const float4*>(VEb + j * CC + c0 + 4);
        float zv[8];
        float ps = 0.f;
#pragma unroll
        for (int cp = 0; cp < 4; cp++) {
            unsigned int lo, hi;
            asm("mov.b64 {%0, %1}, %2;" : "=r"(lo), "=r"(hi) : "l"(acc[jj][cp]));
            const float s0 = __uint_as_float(lo) + bi[cp * 2];
            const float s1 = __uint_as_float(hi) + bi[cp * 2 + 1];
            const float p0 = mk / (1.f + __expf(-s0));
            const float p1 = mk / (1.f + __expf(-s1));
            ps += p0 + p1;
            zv[cp * 2]     = p0;
            zv[cp * 2 + 1] = p1;
        }
        zv[0] *= ve0.x; zv[1] *= ve0.y; zv[2] *= ve0.z; zv[3] *= ve0.w;
        zv[4] *= ve1.x; zv[5] *= ve1.y; zv[6] *= ve1.z; zv[7] *= ve1.w;

        float4* zp = reinterpret_cast<float4*>(zbuf + j * CC + c0);
        zp[0] = make_float4(zv[0], zv[1], zv[2], zv[3]);
        zp[1] = make_float4(zv[4], zv[5], zv[6], zv[7]);
        psum[jj] = ps;
    }

    // warp reduce psum (each warp is a single j-group); lane 0 accumulates
#pragma unroll
    for (int off = 16; off > 0; off >>= 1)
#pragma unroll
        for (int jj = 0; jj < 8; jj++)
            psum[jj] += __shfl_xor_sync(0xffffffffu, psum[jj], off);
    if ((tid & 31) == 0) {
#pragma unroll
        for (int jj = 0; jj < 8; jj++) atomicAdd(&sout2[j0 + jj], psum[jj]);
    }
    __syncthreads();

    // ---- per-column logsumexp over j (thread c = tid; fully coalesced smem reads)
    {
        const int c = tid;
        float m = -1e30f;
#pragma unroll 4
        for (int j = 0; j < TT; j++) m = fmaxf(m, zbuf[j * CC + c]);
        float ssum = 0.f;
#pragma unroll 4
        for (int j = 0; j < TT; j++) ssum += __expf(zbuf[j * CC + c] - m);
        const float lse = __logf(ssum) + m;
        const int row = b * TT + i;
        out[row * CC + c] = x[row * CC + c] + lse;
    }
    if (tid < TT) {
        out[BB * TT * CC + (b * TT + i) * TT + tid] = sout2[tid] * (1.f / 512.f);
    }
}

// ---------------------------------------------------------------------------
extern "C" void kernel_launch(void* const* d_in, const int* in_sizes, int n_in,
                              void* d_out, int out_size)
{
    const float* x     = (const float*)d_in[0];
    const float* ts    = (const float*)d_in[1];
    const float* amask = (const float*)d_in[2];
    const float* Wp    = (const float*)d_in[3];
    const float* bp    = (const float*)d_in[4];
    const float* Wx    = (const float*)d_in[5];
    const float* bx    = (const float*)d_in[6];
    const float* Wt    = (const float*)d_in[7];
    const float* bt    = (const float*)d_in[8];
    const float* Wim   = (const float*)d_in[9];
    const float* bim   = (const float*)d_in[10];
    float* out = (float*)d_out;

    embed_kernel<<<128, 512>>>(x, Wp, bp, Wx, bx);

    const size_t smem = (size_t)(CC * GPITCH + 4 * TT) * sizeof(float);  // 134144 B
    cudaFuncSetAttribute(temporal_kernel, cudaFuncAttributeMaxDynamicSharedMemorySize, (int)smem);
    temporal_kernel<<<BB * TT, 512, smem>>>(x, ts, amask, Wt, bt, Wim, bim, out);
}

// round 3
// speedup vs baseline: 1.0007x; 1.0007x over previous
#include <cuda_runtime.h>
#include <cstdint>

#define BB 16
#define TT 64
#define CC 512
#define GPITCH 65   // padded row pitch (floats) for transposed g tile: kills 32-way STS conflicts

// Scratch (allocation-free rule: __device__ globals)
__device__ float g_VE[BB * TT * CC];   // x @ W_proj + b_proj
__device__ float g_XE[BB * TT * CC];   // x @ W_x    + b_x

// ---------------------------------------------------------------------------
// Kernel 1: both embedding GEMMs fused. 128 blocks x 8 rows, 512 threads.
// thread c owns output column c for 8 rows of both matrices.
// ---------------------------------------------------------------------------
__global__ __launch_bounds__(512) void embed_kernel(
    const float* __restrict__ x,
    const float* __restrict__ Wp, const float* __restrict__ bp,
    const float* __restrict__ Wx, const float* __restrict__ bx)
{
    __shared__ float xs[8 * CC];
    const int tid = threadIdx.x;
    const int r0  = blockIdx.x * 8;

    for (int idx = tid; idx < 8 * CC; idx += 512) xs[idx] = x[r0 * CC + idx];
    __syncthreads();

    const int c = tid;
    float accP[8], accX[8];
#pragma unroll
    for (int r = 0; r < 8; r++) { accP[r] = 0.f; accX[r] = 0.f; }

#pragma unroll 2
    for (int k = 0; k < CC; k++) {
        const float wp = Wp[k * CC + c];
        const float wx = Wx[k * CC + c];
#pragma unroll
        for (int r = 0; r < 8; r++) {
            const float xv = xs[r * CC + k];           // smem broadcast
            accP[r] = fmaf(xv, wp, accP[r]);
            accX[r] = fmaf(xv, wx, accX[r]);
        }
    }

    const float bpv = bp[c], bxv = bx[c];
#pragma unroll
    for (int r = 0; r < 8; r++) {
        g_VE[(r0 + r) * CC + c] = accP[r] + bpv;
        g_XE[(r0 + r) * CC + c] = accX[r] + bxv;
    }
}

// ---------------------------------------------------------------------------
// Kernel 2: one CTA per (b, i). Fused feature build + [64,512]x[512,512] GEMM
// (f32x2 packed FFMA) + sigmoid/mask + logsumexp + mean-over-C.
// ---------------------------------------------------------------------------
__global__ __launch_bounds__(512) void temporal_kernel(
    const float* __restrict__ x,
    const float* __restrict__ ts,
    const float* __restrict__ amask,
    const float* __restrict__ Wt,  const float* __restrict__ bt,
    const float* __restrict__ Wim, const float* __restrict__ bim,
    float* __restrict__ out)
{
    extern __shared__ float sm[];
    float* g     = sm;                    // [512][GPITCH] transposed relu(h); later reused as z[64][512]
    float* feat0 = sm + CC * GPITCH;      // 64
    float* feat1 = feat0 + TT;            // 64
    float* maskv = feat1 + TT;            // 64
    float* sout2 = maskv + TT;            // 64

    const int tid = threadIdx.x;
    const int b   = blockIdx.x >> 6;
    const int i   = blockIdx.x & 63;

    if (tid < TT) {
        const float ti  = ts[b * TT + i];
        const float tj  = ts[b * TT + tid];
        const float rel = ti - tj;
        feat0[tid] = log1pf(fmaxf(rel, 0.f));
        feat1[tid] = log1pf(fmaxf(-rel, 0.f));
        maskv[tid] = amask[b * TT + tid];
        sout2[tid] = 0.f;
    }
    __syncthreads();

    // ---- build g^T[k][j] = relu( f0[j]*Wt[0][k] + f1[j]*Wt[1][k] + bt[k] + XE[b][j][k] )
    {
        const int ck = tid;
        const float w0 = Wt[ck], w1 = Wt[CC + ck], b0 = bt[ck];
        const float* XEb = g_XE + b * TT * CC;
#pragma unroll 4
        for (int j = 0; j < TT; j++) {
            const float h = fmaf(feat0[j], w0, fmaf(feat1[j], w1, b0)) + XEb[j * CC + ck];
            g[ck * GPITCH + j] = fmaxf(h, 0.f);
        }
    }
    __syncthreads();

    // ---- GEMM: out[j][n] = sum_k g[j][k] * Wim[k][n], 8j x 8n per thread
    const int tc = tid & 63;      // n-group 0..63
    const int tjg = tid >> 6;     // j-group 0..7 (warp-uniform)
    const int j0 = tjg * 8;
    const int c0 = tc * 8;

    unsigned long long acc[8][4];
#pragma unroll
    for (int jj = 0; jj < 8; jj++)
#pragma unroll
        for (int cp = 0; cp < 4; cp++) acc[jj][cp] = 0ull;

    const float* Wbase = Wim + c0;
#pragma unroll 2
    for (int k = 0; k < CC; k++) {
        const ulonglong2* wrow = reinterpret_cast<const ulonglong2*>(Wbase + (size_t)k * CC);
        const ulonglong2 wA = wrow[0];   // (w[c0],w[c0+1]) , (w[c0+2],w[c0+3])
        const ulonglong2 wB = wrow[1];
        const float* grow = g + k * GPITCH + j0;
#pragma unroll
        for (int jj = 0; jj < 8; jj++) {
            const float gv = grow[jj];   // smem broadcast (all lanes same j-group? lanes share tjg)
            unsigned long long gp;
            asm("mov.b64 %0, {%1, %1};" : "=l"(gp) : "r"(__float_as_uint(gv)));
            asm("fma.rn.f32x2 %0, %1, %2, %0;" : "+l"(acc[jj][0]) : "l"(gp), "l"(wA.x));
            asm("fma.rn.f32x2 %0, %1, %2, %0;" : "+l"(acc[jj][1]) : "l"(gp), "l"(wA.y));
            asm("fma.rn.f32x2 %0, %1, %2, %0;" : "+l"(acc[jj][2]) : "l"(gp), "l"(wB.x));
            asm("fma.rn.f32x2 %0, %1, %2, %0;" : "+l"(acc[jj][3]) : "l"(gp), "l"(wB.y));
        }
    }
    __syncthreads();   // all g reads finished before we overwrite the region with z

    // ---- epilogue: p = sigmoid(s + b_imp)*mask; z = VE*p; psum for out2
    float bi[8];
#pragma unroll
    for (int cc = 0; cc < 8; cc++) bi[cc] = bim[c0 + cc];

    const float* VEb = g_VE + b * TT * CC;
    float* zbuf = sm;   // reuse as z[j][c], pitch CC (32768 floats < 33280)

    float psum[8];
#pragma unroll
    for (int jj = 0; jj < 8; jj++) {
        const int j = j0 + jj;
        const float mk = maskv[j];
        const float4 ve0 = *reinterpret_cast<const float4*>(VEb + j * CC + c0);
        const float4 ve1 = *reinterpret_cast<const float4*>(VEb + j * CC + c0 + 4);
        float zv[8];
        float ps = 0.f;
#pragma unroll
        for (int cp = 0; cp < 4; cp++) {
            unsigned int lo, hi;
            asm("mov.b64 {%0, %1}, %2;" : "=r"(lo), "=r"(hi) : "l"(acc[jj][cp]));
            const float s0 = __uint_as_float(lo) + bi[cp * 2];
            const float s1 = __uint_as_float(hi) + bi[cp * 2 + 1];
            const float p0 = mk / (1.f + __expf(-s0));
            const float p1 = mk / (1.f + __expf(-s1));
            ps += p0 + p1;
            zv[cp * 2]     = p0;
            zv[cp * 2 + 1] = p1;
        }
        zv[0] *= ve0.x; zv[1] *= ve0.y; zv[2] *= ve0.z; zv[3] *= ve0.w;
        zv[4] *= ve1.x; zv[5] *= ve1.y; zv[6] *= ve1.z; zv[7] *= ve1.w;

        float4* zp = reinterpret_cast<float4*>(zbuf + j * CC + c0);
        zp[0] = make_float4(zv[0], zv[1], zv[2], zv[3]);
        zp[1] = make_float4(zv[4], zv[5], zv[6], zv[7]);
        psum[jj] = ps;
    }

    // warp reduce psum (each warp is a single j-group); lane 0 accumulates
#pragma unroll
    for (int off = 16; off > 0; off >>= 1)
#pragma unroll
        for (int jj = 0; jj < 8; jj++)
            psum[jj] += __shfl_xor_sync(0xffffffffu, psum[jj], off);
    if ((tid & 31) == 0) {
#pragma unroll
        for (int jj = 0; jj < 8; jj++) atomicAdd(&sout2[j0 + jj], psum[jj]);
    }
    __syncthreads();

    // ---- per-column logsumexp over j (thread c = tid; fully coalesced smem reads)
    {
        const int c = tid;
        float m = -1e30f;
#pragma unroll 4
        for (int j = 0; j < TT; j++) m = fmaxf(m, zbuf[j * CC + c]);
        float ssum = 0.f;
#pragma unroll 4
        for (int j = 0; j < TT; j++) ssum += __expf(zbuf[j * CC + c] - m);
        const float lse = __logf(ssum) + m;
        const int row = b * TT + i;
        out[row * CC + c] = x[row * CC + c] + lse;
    }
    if (tid < TT) {
        out[BB * TT * CC + (b * TT + i) * TT + tid] = sout2[tid] * (1.f / 512.f);
    }
}

// ---------------------------------------------------------------------------
extern "C" void kernel_launch(void* const* d_in, const int* in_sizes, int n_in,
                              void* d_out, int out_size)
{
    const float* x     = (const float*)d_in[0];
    const float* ts    = (const float*)d_in[1];
    const float* amask = (const float*)d_in[2];
    const float* Wp    = (const float*)d_in[3];
    const float* bp    = (const float*)d_in[4];
    const float* Wx    = (const float*)d_in[5];
    const float* bx    = (const float*)d_in[6];
    const float* Wt    = (const float*)d_in[7];
    const float* bt    = (const float*)d_in[8];
    const float* Wim   = (const float*)d_in[9];
    const float* bim   = (const float*)d_in[10];
    float* out = (float*)d_out;

    embed_kernel<<<128, 512>>>(x, Wp, bp, Wx, bx);

    const size_t smem = (size_t)(CC * GPITCH + 4 * TT) * sizeof(float);  // 134144 B
    cudaFuncSetAttribute(temporal_kernel, cudaFuncAttributeMaxDynamicSharedMemorySize, (int)smem);
    temporal_kernel<<<BB * TT, 512, smem>>>(x, ts, amask, Wt, bt, Wim, bim, out);
}